// round 14
// baseline (speedup 1.0000x reference)
#include <cuda_runtime.h>
#include <math.h>

// ---------------------------------------------------------------------------
// MyDetector: YOLO decode + threshold + top-300 + greedy NMS.
// K1: 512 CTAs (8 slices x 64 images) decode survivors into fixed per-slice
//     scratch (no zeroing pass, no global atomics).
// K2: 64 CTAs gather ~66 survivors/image, rank-sort by (conf desc, orig asc)
//     == jax.lax.top_k order, bitmask greedy NMS, emit 300 rows.
// ---------------------------------------------------------------------------

#define HW13 169
#define HW26 676
#define HW52 2704
#define NB13 (3 * HW13)                  // 507
#define NB26 (3 * HW26)                  // 2028
#define NB52 (3 * HW52)                  // 8112
#define NBOX (NB13 + NB26 + NB52)        // 10647
#define SLICES 8
#define SLICE  1344                      // 8*1344 = 10752 >= NBOX
#define SCAP   128                       // per-slice survivor cap (mean ~8)
#define VMAX   (SLICES * SCAP)           // 1024
#define KDET   300
#define MAXN   64
#define NWRD   ((KDET + 63) / 64)        // 5
#define T1     256
#define K1IT   (SLICE / T1)              // 6 (SLICE % T1 == 0? 1344/256=5.25) -> use ceil
#undef  K1IT
#define K1IT   ((SLICE + T1 - 1) / T1)   // 6

struct Rec { float conf, ox, oy, w, h, cls; int orig; int pad; };

__device__ Rec g_rec[MAXN * SLICES * SCAP];
__device__ int g_scnt[MAXN * SLICES];

// ---- coalesced conf load with compile-time-constant divisions ----
__device__ __forceinline__ float conf_at(int t, long n,
    const float* __restrict__ o13, const float* __restrict__ o26,
    const float* __restrict__ o52)
{
    if (t < NB13) {
        int a = t / HW13, cell = t - a * HW13;
        return __ldg(o13 + (n * 255 + (long)a * 85) * HW13 + cell);
    } else if (t < NB13 + NB26) {
        int u = t - NB13;
        int a = u / HW26, cell = u - a * HW26;
        return __ldg(o26 + (n * 255 + (long)a * 85) * HW26 + cell);
    } else {
        int u = t - NB13 - NB26;
        int a = u / HW52, cell = u - a * HW52;
        return __ldg(o52 + (n * 255 + (long)a * 85) * HW52 + cell);
    }
}

// ---- warp-cooperative decode of one candidate (32 lanes split 80 classes) ----
template<int HW, int W>
__device__ __forceinline__ void warp_decode(const float* __restrict__ src,
    const float* __restrict__ anc, float stride, int off,
    long n, int u, int lane, float conf, Rec* dst)
{
    int a    = u / HW;            // constant divisor -> mul/shift
    int cell = u - a * HW;
    const float* base = src + (n * 255 + (long)a * 85) * HW + cell;

    float v0 = __ldg(base + (long)(5 + lane) * HW);
    float v1 = __ldg(base + (long)(37 + lane) * HW);
    float v2 = (lane < 16) ? __ldg(base + (long)(69 + lane) * HW) : -1e30f;
    float coord = (lane < 4) ? __ldg(base + (long)(1 + lane) * HW) : 0.0f;

    float bv = v0; int bi = lane;
    if (v1 > bv) { bv = v1; bi = lane + 32; }
    if (lane < 16 && v2 > bv) { bv = v2; bi = lane + 64; }
    #pragma unroll
    for (int o = 16; o > 0; o >>= 1) {
        float ov = __shfl_down_sync(0xffffffffu, bv, o);
        int   oi = __shfl_down_sync(0xffffffffu, bi, o);
        if (ov > bv || (ov == bv && oi < bi)) { bv = ov; bi = oi; }
    }
    float tx = __shfl_sync(0xffffffffu, coord, 0);
    float ty = __shfl_sync(0xffffffffu, coord, 1);
    float tw = __shfl_sync(0xffffffffu, coord, 2);
    float th = __shfl_sync(0xffffffffu, coord, 3);

    if (lane == 0) {
        int x = cell % W, y = cell / W;
        Rec r;
        r.conf = conf;
        r.ox   = ((float)x + tx) * stride;
        r.oy   = ((float)y + ty) * stride;
        r.w    = expf(tw) * __ldg(anc + 2 * a + 0);
        r.h    = expf(th) * __ldg(anc + 2 * a + 1);
        r.cls  = (float)bi;
        r.orig = off + cell * 3 + a;   // reference flat index (anchor innermost)
        r.pad  = 0;
        *dst = r;
    }
}

// ============================ K1: decode ============================
__global__ __launch_bounds__(T1)
void decode_kernel(const float* __restrict__ o13,
                   const float* __restrict__ o26,
                   const float* __restrict__ o52,
                   const float* __restrict__ a13,
                   const float* __restrict__ a26,
                   const float* __restrict__ a52,
                   const float* __restrict__ tptr)
{
    __shared__ int   s_cnt;
    __shared__ float s_conf[SCAP];
    __shared__ int   s_t[SCAP];

    const int  sl  = blockIdx.x;
    const long n   = blockIdx.y;
    const int  tid = threadIdx.x;
    const int  wid = tid >> 5;
    const int  lane = tid & 31;

    if (tid == 0) s_cnt = 0;
    __syncthreads();

    const float thr = *tptr;
    const int t0 = sl * SLICE;

    // batched conf loads (up to 6 in flight per thread)
    float cv[K1IT];
    #pragma unroll
    for (int k = 0; k < K1IT; ++k) {
        int t = t0 + k * T1 + tid;
        cv[k] = (t < NBOX && t < t0 + SLICE) ? conf_at(t, n, o13, o26, o52) : -1e30f;
    }
    #pragma unroll
    for (int k = 0; k < K1IT; ++k) {
        if (cv[k] > thr) {
            int slot = atomicAdd(&s_cnt, 1);
            if (slot < SCAP) { s_conf[slot] = cv[k]; s_t[slot] = t0 + k * T1 + tid; }
        }
    }
    __syncthreads();

    int C = s_cnt;
    if (C > SCAP) C = SCAP;

    Rec* dst0 = g_rec + (n * SLICES + sl) * SCAP;

    // warp per candidate
    for (int c = wid; c < C; c += (T1 / 32)) {
        int t = s_t[c];
        float conf = s_conf[c];
        if (t < NB13)
            warp_decode<HW13, 13>(o13, a13, 32.f, 0, n, t, lane, conf, dst0 + c);
        else if (t < NB13 + NB26)
            warp_decode<HW26, 26>(o26, a26, 16.f, NB13, n, t - NB13, lane, conf, dst0 + c);
        else
            warp_decode<HW52, 52>(o52, a52, 8.f, NB13 + NB26, n, t - NB13 - NB26, lane, conf, dst0 + c);
    }

    if (tid == 0) g_scnt[n * SLICES + sl] = C;
}

// ============================ K2: sort + NMS + emit ============================
__global__ __launch_bounds__(T1)
void nms_kernel(float* __restrict__ out)
{
    __shared__ int   s_c[SLICES], s_st[SLICES];
    __shared__ int   s_V;
    __shared__ float s_conf[VMAX];
    __shared__ int   s_origi[VMAX];
    __shared__ int   s_gidx[VMAX];
    __shared__ float s_box[KDET][6];
    __shared__ float s_cor[KDET][4];
    __shared__ float s_area[KDET];
    __shared__ int   s_keep[KDET];
    __shared__ unsigned long long s_sup[KDET][NWRD];

    const long n   = blockIdx.x;
    const int  tid = threadIdx.x;

    if (tid < SLICES) s_c[tid] = g_scnt[n * SLICES + tid];
    __syncthreads();
    if (tid == 0) {
        int acc = 0;
        #pragma unroll
        for (int s = 0; s < SLICES; ++s) { s_st[s] = acc; acc += s_c[s]; }
        s_V = acc;
    }
    __syncthreads();

    const int V = s_V;                        // <= VMAX by construction
    const int M = (V < KDET) ? V : KDET;

    // gather (conf, orig, global index) into compact shared arrays
    #pragma unroll
    for (int s = 0; s < SLICES; ++s) {
        int cs = s_c[s], st = s_st[s];
        for (int i = tid; i < cs; i += T1) {
            int g = (int)((n * SLICES + s) * SCAP + i);
            s_conf[st + i]  = g_rec[g].conf;
            s_origi[st + i] = g_rec[g].orig;
            s_gidx[st + i]  = g;
        }
    }
    __syncthreads();

    // rank sort by (conf desc, orig asc) == jax.lax.top_k order
    for (int i = tid; i < V; i += T1) {
        float si = s_conf[i];
        int   oi = s_origi[i];
        int   rank = 0;
        for (int j = 0; j < V; ++j) {
            float sj = s_conf[j];
            rank += (sj > si) || (sj == si && s_origi[j] < oi);
        }
        if (rank < KDET) {
            Rec r = g_rec[s_gidx[i]];
            s_box[rank][0] = r.conf; s_box[rank][1] = r.ox; s_box[rank][2] = r.oy;
            s_box[rank][3] = r.w;    s_box[rank][4] = r.h;  s_box[rank][5] = r.cls;
            float x1 = r.ox - r.w * 0.5f, y1 = r.oy - r.h * 0.5f;
            float x2 = r.ox + r.w * 0.5f, y2 = r.oy + r.h * 0.5f;
            s_cor[rank][0] = x1; s_cor[rank][1] = y1;
            s_cor[rank][2] = x2; s_cor[rank][3] = y2;
            s_area[rank]   = (x2 - x1) * (y2 - y1);
        }
    }
    __syncthreads();

    // suppression bitmasks, one row per thread (j < i only)
    for (int i = tid; i < M; i += T1) {
        unsigned long long mw[NWRD];
        #pragma unroll
        for (int w = 0; w < NWRD; ++w) mw[w] = 0ull;
        float xi1 = s_cor[i][0], yi1 = s_cor[i][1];
        float xi2 = s_cor[i][2], yi2 = s_cor[i][3];
        float ai  = s_area[i];
        float ci  = s_box[i][5];
        for (int j = 0; j < i; ++j) {
            if (s_box[j][5] == ci) {
                float ix1 = fmaxf(xi1, s_cor[j][0]);
                float iy1 = fmaxf(yi1, s_cor[j][1]);
                float ix2 = fminf(xi2, s_cor[j][2]);
                float iy2 = fminf(yi2, s_cor[j][3]);
                float iw = fmaxf(ix2 - ix1, 0.0f);
                float ih = fmaxf(iy2 - iy1, 0.0f);
                float inter = iw * ih;
                float uni   = ai + s_area[j] - inter;
                if (inter / fmaxf(uni, 1e-9f) > 0.3f)
                    mw[j >> 6] |= 1ull << (j & 63);
            }
        }
        #pragma unroll
        for (int w = 0; w < NWRD; ++w) s_sup[i][w] = mw[w];
    }
    __syncthreads();

    // sequential greedy scan on bitmasks
    if (tid == 0) {
        unsigned long long kw[NWRD];
        #pragma unroll
        for (int w = 0; w < NWRD; ++w) kw[w] = 0ull;
        for (int i = 0; i < M; ++i) {
            unsigned long long hit = 0ull;
            #pragma unroll
            for (int w = 0; w < NWRD; ++w) hit |= (s_sup[i][w] & kw[w]);
            int keep = (hit == 0ull);
            s_keep[i] = keep;
            if (keep) kw[i >> 6] |= 1ull << (i & 63);
        }
    }
    __syncthreads();

    // emit all 300 rows
    float* po = out + n * KDET * 7;
    for (int r = tid; r < KDET; r += T1) {
        float v0 = 0.f, v1 = 0.f, v2 = 0.f, v3 = 0.f, v4 = 0.f, v5 = 0.f, v6 = 0.f;
        if (r < M && s_keep[r]) {
            v0 = s_box[r][0]; v1 = s_box[r][1]; v2 = s_box[r][2];
            v3 = s_box[r][3]; v4 = s_box[r][4]; v5 = s_box[r][5];
            v6 = (float)n;
        }
        float* pr = po + (long)r * 7;
        pr[0] = v0; pr[1] = v1; pr[2] = v2; pr[3] = v3;
        pr[4] = v4; pr[5] = v5; pr[6] = v6;
    }
}

extern "C" void kernel_launch(void* const* d_in, const int* in_sizes, int n_in,
                              void* d_out, int out_size)
{
    const float* o13 = (const float*)d_in[0];
    const float* o26 = (const float*)d_in[1];
    const float* o52 = (const float*)d_in[2];
    const float* a13 = (const float*)d_in[3];
    const float* a26 = (const float*)d_in[4];
    const float* a52 = (const float*)d_in[5];
    const float* thr = (const float*)d_in[6];

    int N = in_sizes[0] / (255 * HW13);
    if (N > MAXN) N = MAXN;

    dim3 g1(SLICES, N);
    decode_kernel<<<g1, T1>>>(o13, o26, o52, a13, a26, a52, thr);
    nms_kernel<<<N, T1>>>((float*)d_out);
}